// round 14
// baseline (speedup 1.0000x reference)
#include <cuda_runtime.h>
#include <cuda_bf16.h>
#include <math.h>
#include <stdint.h>

// Problem constants
#define BB   128     // batch
#define TT   1024    // seq
#define DD   128     // in_dim
#define UU   256     // units
#define GG   768     // 3*units (r|u|c)
#define KK3  384     // 3*in_dim (x_t | x_{t-1} | x_{t-2})
#define MTOT (BB * TT)

// ---------------------------------------------------------------------------
// PTX helpers (baseline PTX only — no sm_103a-only features)
// ---------------------------------------------------------------------------
#define CLUSTER_SYNC() do { \
    asm volatile("barrier.cluster.arrive.aligned;" ::: "memory"); \
    asm volatile("barrier.cluster.wait.aligned;" ::: "memory"); \
} while (0)

// remote SMEM stores with inline mapa (no live remote-address registers)
__device__ __forceinline__ void dsmem_store_u64(uint32_t saddr, uint32_t rank,
                                                unsigned long long v) {
    uint32_t remote;
    asm("mapa.shared::cluster.u32 %0, %1, %2;" : "=r"(remote) : "r"(saddr), "r"(rank));
    asm volatile("st.shared::cluster.b64 [%0], %1;" :: "r"(remote), "l"(v) : "memory");
}

// cp.async (sm_80+ baseline)
__device__ __forceinline__ void cp_async16(uint32_t smem, const void* g) {
    asm volatile("cp.async.cg.shared.global [%0], [%1], 16;" :: "r"(smem), "l"(g) : "memory");
}
__device__ __forceinline__ void cp_async8(uint32_t smem, const void* g) {
    asm volatile("cp.async.ca.shared.global [%0], [%1], 8;" :: "r"(smem), "l"(g) : "memory");
}
__device__ __forceinline__ void cp_async4(uint32_t smem, const void* g) {
    asm volatile("cp.async.ca.shared.global [%0], [%1], 4;" :: "r"(smem), "l"(g) : "memory");
}
#define CP_COMMIT() asm volatile("cp.async.commit_group;" ::: "memory")
#define CP_WAIT1()  asm volatile("cp.async.wait_group 1;" ::: "memory")

// bf16 m16n8k16 MMA (fragment layouts verified in rounds 5-13)
#define MMA_BF16(d, a, b) \
    asm volatile("mma.sync.aligned.m16n8k16.row.col.f32.bf16.bf16.f32 " \
        "{%0,%1,%2,%3}, {%4,%5,%6,%7}, {%8,%9}, {%0,%1,%2,%3};" \
        : "+f"((d)[0]), "+f"((d)[1]), "+f"((d)[2]), "+f"((d)[3]) \
        : "r"((a)[0]), "r"((a)[1]), "r"((a)[2]), "r"((a)[3]), "r"((b)[0]), "r"((b)[1]))

// split (a,b) fp32 pair into packed bf16x2 hi and lo words (low half = a)
__device__ __forceinline__ void split_pack(float a, float b, uint32_t& hi, uint32_t& lo) {
    __nv_bfloat16 ah = __float2bfloat16_rn(a), bh = __float2bfloat16_rn(b);
    __nv_bfloat16 al = __float2bfloat16_rn(a - __bfloat162float(ah));
    __nv_bfloat16 bl = __float2bfloat16_rn(b - __bfloat162float(bh));
    __nv_bfloat162 h2; h2.x = ah; h2.y = bh;
    __nv_bfloat162 l2; l2.x = al; l2.y = bl;
    hi = *reinterpret_cast<uint32_t*>(&h2);
    lo = *reinterpret_cast<uint32_t*>(&l2);
}

// ---------------------------------------------------------------------------
// Scratch (device globals: no allocations allowed)
// ---------------------------------------------------------------------------
__device__ __nv_bfloat16 g_xhi[(size_t)MTOT * DD];     // 32 MB
__device__ __nv_bfloat16 g_xlo[(size_t)MTOT * DD];     // 32 MB
__device__ __nv_bfloat16 g_WThi[GG * KK3];             // combined weights, [col][k3] K-major
__device__ __nv_bfloat16 g_WTlo[GG * KK3];
__device__ float g_Pre[(size_t)BB * TT * GG];          // pre-activations (402 MB)

// ---------------------------------------------------------------------------
// Kernel 1: build combined input weights, K-major, bf16 hi/lo split.
// ---------------------------------------------------------------------------
__global__ void split_w_kernel(const float* __restrict__ iw) {
    int idx = blockIdx.x * blockDim.x + threadIdx.x;
    if (idx >= GG * KK3) return;
    int j  = idx / KK3;
    int k3 = idx - j * KK3;
    int gate = j >> 8;
    int ju   = j & 255;
    int s    = k3 >> 7;
    int k    = k3 & 127;
    const float* row = iw + (size_t)k * (7 * UU);
    float v = 0.f;
    if (gate == 0) {
        float W = row[0 * UU + ju], dW = row[3 * UU + ju], ddW = row[5 * UU + ju];
        v = (s == 0) ? (W + dW + ddW) : (s == 1) ? -(dW + 2.f * ddW) : ddW;
    } else if (gate == 1) {
        float W = row[1 * UU + ju], dW = row[4 * UU + ju], ddW = row[6 * UU + ju];
        v = (s == 0) ? (W + dW + ddW) : (s == 1) ? -(dW + 2.f * ddW) : ddW;
    } else {
        v = (s == 0) ? row[2 * UU + ju] : 0.f;
    }
    __nv_bfloat16 hi = __float2bfloat16_rn(v);
    __nv_bfloat16 lo = __float2bfloat16_rn(v - __bfloat162float(hi));
    g_WThi[idx] = hi;
    g_WTlo[idx] = lo;
}

// ---------------------------------------------------------------------------
// Kernel 2: split x into bf16 hi/lo (4 elems per thread).
// ---------------------------------------------------------------------------
__global__ void split_x_kernel(const float* __restrict__ x) {
    size_t i4 = (size_t)blockIdx.x * blockDim.x + threadIdx.x;
    float4 v = reinterpret_cast<const float4*>(x)[i4];
    __nv_bfloat16 h0 = __float2bfloat16_rn(v.x), h1 = __float2bfloat16_rn(v.y);
    __nv_bfloat16 h2 = __float2bfloat16_rn(v.z), h3 = __float2bfloat16_rn(v.w);
    __nv_bfloat16 l0 = __float2bfloat16_rn(v.x - __bfloat162float(h0));
    __nv_bfloat16 l1 = __float2bfloat16_rn(v.y - __bfloat162float(h1));
    __nv_bfloat16 l2 = __float2bfloat16_rn(v.z - __bfloat162float(h2));
    __nv_bfloat16 l3 = __float2bfloat16_rn(v.w - __bfloat162float(h3));
    __nv_bfloat16 hv[4] = {h0, h1, h2, h3};
    __nv_bfloat16 lv[4] = {l0, l1, l2, l3};
    reinterpret_cast<uint2*>(g_xhi)[i4] = *reinterpret_cast<uint2*>(hv);
    reinterpret_cast<uint2*>(g_xlo)[i4] = *reinterpret_cast<uint2*>(lv);
}

// ---------------------------------------------------------------------------
// Kernel 3: tensor precompute — K=64 sub-chunks, cp.async double buffering
// (round-12 version, proven).
// ---------------------------------------------------------------------------
#define TS2       72
#define SUB_FL    (128 * TS2)
#define SUB_BYTES (SUB_FL * 2)
#define BUF_BYTES (4 * SUB_BYTES)
#define MP_SMEM_BYTES (2 * BUF_BYTES)

__device__ __forceinline__ void ld_sub_A(char* smem_gen, uint32_t sbase,
                                         const __nv_bfloat16* __restrict__ src,
                                         int m0, int s, int half, int tid) {
#pragma unroll
    for (int i = 0; i < 4; i++) {
        int idx = tid + i * 256;
        int r   = idx >> 3;
        int c8  = (idx & 7) << 3;
        int m   = m0 + r;
        uint32_t off = (uint32_t)((r * TS2 + c8) * 2);
        if ((m & (TT - 1)) >= s)
            cp_async16(sbase + off, src + (size_t)(m - s) * DD + half * 64 + c8);
        else
            *reinterpret_cast<uint4*>(smem_gen + off) = make_uint4(0u, 0u, 0u, 0u);
    }
}

__device__ __forceinline__ void ld_sub_B(uint32_t sbase,
                                         const __nv_bfloat16* __restrict__ src,
                                         int n0, int s, int half, int tid) {
#pragma unroll
    for (int i = 0; i < 4; i++) {
        int idx = tid + i * 256;
        int r   = idx >> 3;
        int c8  = (idx & 7) << 3;
        uint32_t off = (uint32_t)((r * TS2 + c8) * 2);
        cp_async16(sbase + off, src + (size_t)(n0 + r) * KK3 + s * 128 + half * 64 + c8);
    }
}

__global__ void __launch_bounds__(256, 1) mma_pre_kernel(const float* __restrict__ bias) {
    extern __shared__ char smc[];
    const uint32_t sb = (uint32_t)__cvta_generic_to_shared(smc);

    const int tid  = threadIdx.x;
    const int wid  = tid >> 5;
    const int lane = tid & 31;
    const int wm   = wid & 3;
    const int wn   = wid >> 2;
    const int m0 = blockIdx.x * 128;
    const int n0 = blockIdx.y * 128;
    const int Q  = (n0 < 512) ? 6 : 2;

    const int qa = (lane & 3) * 2;
    const int gp = lane >> 2;

    float acc[2][8][4];
#pragma unroll
    for (int mf = 0; mf < 2; mf++)
#pragma unroll
        for (int nf = 0; nf < 8; nf++)
#pragma unroll
            for (int q = 0; q < 4; q++) acc[mf][nf][q] = 0.f;

    ld_sub_A(smc, sb + 0 * SUB_BYTES, g_xhi, m0, 0, 0, tid);
    ld_sub_A(smc + SUB_BYTES, sb + 1 * SUB_BYTES, g_xlo, m0, 0, 0, tid);
    ld_sub_B(sb + 2 * SUB_BYTES, g_WThi, n0, 0, 0, tid);
    ld_sub_B(sb + 3 * SUB_BYTES, g_WTlo, n0, 0, 0, tid);
    CP_COMMIT();

    for (int q = 0; q < Q; q++) {
        const int bc = q & 1, bn = bc ^ 1;
        if (q + 1 < Q) {
            int s2 = (q + 1) >> 1, h2 = (q + 1) & 1;
            char*    gb = smc + bn * BUF_BYTES;
            uint32_t ab = sb + (uint32_t)bn * BUF_BYTES;
            ld_sub_A(gb, ab + 0 * SUB_BYTES, g_xhi, m0, s2, h2, tid);
            ld_sub_A(gb + SUB_BYTES, ab + 1 * SUB_BYTES, g_xlo, m0, s2, h2, tid);
            ld_sub_B(ab + 2 * SUB_BYTES, g_WThi, n0, s2, h2, tid);
            ld_sub_B(ab + 3 * SUB_BYTES, g_WTlo, n0, s2, h2, tid);
        }
        CP_COMMIT();
        CP_WAIT1();
        __syncthreads();

        const __nv_bfloat16* Ahi = reinterpret_cast<__nv_bfloat16*>(smc + bc * BUF_BYTES);
        const __nv_bfloat16* Alo = Ahi + SUB_FL;
        const __nv_bfloat16* Bhi = Alo + SUB_FL;
        const __nv_bfloat16* Blo = Bhi + SUB_FL;

#pragma unroll
        for (int ks = 0; ks < 4; ks++) {
            const int k0 = ks * 16;
            uint32_t ah[2][4], al[2][4];
#pragma unroll
            for (int mf = 0; mf < 2; mf++) {
                int r = wm * 32 + mf * 16 + gp;
                ah[mf][0] = *reinterpret_cast<const uint32_t*>(&Ahi[r * TS2 + k0 + qa]);
                ah[mf][1] = *reinterpret_cast<const uint32_t*>(&Ahi[(r + 8) * TS2 + k0 + qa]);
                ah[mf][2] = *reinterpret_cast<const uint32_t*>(&Ahi[r * TS2 + k0 + 8 + qa]);
                ah[mf][3] = *reinterpret_cast<const uint32_t*>(&Ahi[(r + 8) * TS2 + k0 + 8 + qa]);
                al[mf][0] = *reinterpret_cast<const uint32_t*>(&Alo[r * TS2 + k0 + qa]);
                al[mf][1] = *reinterpret_cast<const uint32_t*>(&Alo[(r + 8) * TS2 + k0 + qa]);
                al[mf][2] = *reinterpret_cast<const uint32_t*>(&Alo[r * TS2 + k0 + 8 + qa]);
                al[mf][3] = *reinterpret_cast<const uint32_t*>(&Alo[(r + 8) * TS2 + k0 + 8 + qa]);
            }
            uint32_t bh[8][2], bl[8][2];
#pragma unroll
            for (int nf = 0; nf < 8; nf++) {
                int n = wn * 64 + nf * 8 + gp;
                bh[nf][0] = *reinterpret_cast<const uint32_t*>(&Bhi[n * TS2 + k0 + qa]);
                bh[nf][1] = *reinterpret_cast<const uint32_t*>(&Bhi[n * TS2 + k0 + 8 + qa]);
                bl[nf][0] = *reinterpret_cast<const uint32_t*>(&Blo[n * TS2 + k0 + qa]);
                bl[nf][1] = *reinterpret_cast<const uint32_t*>(&Blo[n * TS2 + k0 + 8 + qa]);
            }
#pragma unroll
            for (int mf = 0; mf < 2; mf++)
#pragma unroll
                for (int nf = 0; nf < 8; nf++) {
                    MMA_BF16(acc[mf][nf], ah[mf], bh[nf]);
                    MMA_BF16(acc[mf][nf], ah[mf], bl[nf]);
                    MMA_BF16(acc[mf][nf], al[mf], bh[nf]);
                }
        }
        __syncthreads();
    }

#pragma unroll
    for (int nf = 0; nf < 8; nf++) {
        int col = n0 + wn * 64 + nf * 8 + qa;
        float2 bz = *reinterpret_cast<const float2*>(bias + col);
#pragma unroll
        for (int mf = 0; mf < 2; mf++) {
            int row = m0 + wm * 32 + mf * 16 + gp;
            float2 v0, v1;
            v0.x = acc[mf][nf][0] + bz.x;
            v0.y = acc[mf][nf][1] + bz.y;
            v1.x = acc[mf][nf][2] + bz.x;
            v1.y = acc[mf][nf][3] + bz.y;
            *reinterpret_cast<float2*>(&g_Pre[(size_t)row * GG + col]) = v0;
            *reinterpret_cast<float2*>(&g_Pre[(size_t)(row + 8) * GG + col]) = v1;
        }
    }
}

// ---------------------------------------------------------------------------
// Kernel 4: HMMA recurrence — R13 structure (interleaved hi/lo rows, fused
// u64 exchange) + round-14 delta: the 4-rank broadcast is SPLIT across lane
// pairs. Even lanes store ranks {0,1}; their odd neighbors receive the packed
// value via one shfl and store ranks {2,3}. Store chain per producer: 4 -> 2.
// Values/addresses bitwise identical; only the issuing lane changes.
// ---------------------------------------------------------------------------
__global__ void __launch_bounds__(512, 1) __cluster_dims__(4, 1, 1)
rnn_kernel(const float* __restrict__ Wh, float* __restrict__ out) {
    __shared__ uint32_t hAp[1024];    // [128 unit-pairs][8 rows] interleaved hi/lo
    __shared__ uint32_t rhAp[1024];
    __shared__ float h4f[1024];       // [unit][row] fp32 hidden state
    __shared__ float uS[256];         // [row][col] update gate slice
    __shared__ float red[512];        // [kh][row][col] phase2 reduction
    __shared__ float2 p1buf[2][256];  // prefetched phase-1 pre-activations
    __shared__ float  p2buf[2][256];  // prefetched cand pre-activations

    const int tid  = threadIdx.x;
    const int w    = tid >> 5;
    const int lane = tid & 31;
    const int gp   = lane >> 2;
    const int tg   = lane & 3;
    const int qa   = tg * 2;
    uint32_t cr;
    asm("mov.u32 %0, %%cluster_ctarank;" : "=r"(cr));
    const int b0 = (blockIdx.x >> 2) * 4;

    // ---- one-time: load weight fragments into registers (bf16 hi/lo) ----
    uint32_t b1h[16][2], b1l[16][2];
    {
        int gcol = (w < 8) ? ((int)cr * 64 + w * 8 + gp)
                           : (256 + (int)cr * 64 + (w - 8) * 8 + gp);
#pragma unroll
        for (int ch = 0; ch < 16; ch++) {
            int k0 = ch * 16;
            float v00 = Wh[(size_t)(k0 + qa) * GG + gcol];
            float v01 = Wh[(size_t)(k0 + qa + 1) * GG + gcol];
            float v10 = Wh[(size_t)(k0 + 8 + qa) * GG + gcol];
            float v11 = Wh[(size_t)(k0 + 8 + qa + 1) * GG + gcol];
            split_pack(v00, v01, b1h[ch][0], b1l[ch][0]);
            split_pack(v10, v11, b1h[ch][1], b1l[ch][1]);
        }
    }
    const int ns = w & 7, kh = w >> 3;
    uint32_t b2h[8][2], b2l[8][2];
    {
        int gcol = 512 + (int)cr * 64 + ns * 8 + gp;
#pragma unroll
        for (int ch = 0; ch < 8; ch++) {
            int k0 = kh * 128 + ch * 16;
            float v00 = Wh[(size_t)(k0 + qa) * GG + gcol];
            float v01 = Wh[(size_t)(k0 + qa + 1) * GG + gcol];
            float v10 = Wh[(size_t)(k0 + 8 + qa) * GG + gcol];
            float v11 = Wh[(size_t)(k0 + 8 + qa + 1) * GG + gcol];
            split_pack(v00, v01, b2h[ch][0], b2l[ch][0]);
            split_pack(v10, v11, b2h[ch][1], b2l[ch][1]);
        }
    }

    // ---- init state ----
    for (int i = tid; i < 1024; i += 512) { hAp[i] = 0u; h4f[i] = 0.f; }
    const uint32_t rh_base = (uint32_t)__cvta_generic_to_shared(rhAp);
    const uint32_t hA_base = (uint32_t)__cvta_generic_to_shared(hAp);
    __syncthreads();
    CLUSTER_SYNC();

    // finalize-2 identities
    const int r2 = (tid >> 6) & 3;
    const int c2 = tid & 63;
    const float* p2ptr = g_Pre + (size_t)(b0 + r2) * TT * GG + 512 + cr * 64 + c2;
    float* outp = out + ((size_t)(b0 + r2) * TT) * UU + cr * 64 + c2;

    // phase-1 p1 prefetch pointer (prefetching lanes 0-15: batch = gp, col qa)
    const int colbase1 = (w < 8) ? ((int)cr * 64 + w * 8 + qa)
                                 : (256 + (int)cr * 64 + (w - 8) * 8 + qa);
    const float* p1ptr = g_Pre + (size_t)(b0 + (gp & 3)) * TT * GG + colbase1;

    const uint32_t p1slot = (uint32_t)__cvta_generic_to_shared(&p1buf[0][w * 16 + lane]);
    const uint32_t p2slot = (uint32_t)__cvta_generic_to_shared(&p2buf[0][tid]);

    // prologue: prefetch step 0
    if (lane < 16) cp_async8(p1slot, p1ptr);
    if (tid < 256) cp_async4(p2slot, p2ptr);
    CP_COMMIT();

    for (int t = 0; t < TT; t++) {
        const int tn = (t + 1) & (TT - 1);
        const int bc = t & 1, bn = bc ^ 1;

        if (lane < 16) cp_async8(p1slot + (uint32_t)bn * 2048u, p1ptr + (size_t)tn * GG);
        if (tid < 256) cp_async4(p2slot + (uint32_t)bn * 1024u, p2ptr + (size_t)tn * GG);
        CP_COMMIT();

        // ---- phase 1: h @ [Whr|Whu] strip, split hi/lo chains ----
        float chA[4] = {0.f, 0.f, 0.f, 0.f};
        float clA[4] = {0.f, 0.f, 0.f, 0.f};
#pragma unroll
        for (int ch = 0; ch < 16; ch++) {
            uint32_t a[4];
            a[0] = hAp[(ch * 8 + tg) * 8 + gp];
            a[2] = hAp[(ch * 8 + tg + 4) * 8 + gp];
            a[1] = 0u; a[3] = 0u;
            MMA_BF16(chA, a, b1h[ch]);
            MMA_BF16(clA, a, b1l[ch]);
        }
        CP_WAIT1();
        float v0 = chA[0] + clA[0];
        float v1 = chA[1] + clA[1];
        v0 += __shfl_down_sync(0xffffffffu, v0, 4);   // row 2b + row 2b+1 (hi+lo)
        v1 += __shfl_down_sync(0xffffffffu, v1, 4);
        unsigned long long pv1 = 0ull;
        if (!(gp & 1)) {
            const int b = gp >> 1;                    // batch row 0..3
            float2 p1 = p1buf[bc][w * 16 + b * 4 + tg];
            v0 += p1.x; v1 += p1.y;
            float sg0 = 1.f / (1.f + __expf(-v0));
            float sg1 = 1.f / (1.f + __expf(-v1));
            if (w < 8) {   // r-gate: produce packed rh word pair
                int u0 = (int)cr * 64 + w * 8 + qa;
                float rh0 = sg0 * h4f[u0 * 4 + b];
                float rh1 = sg1 * h4f[(u0 + 1) * 4 + b];
                uint32_t whi, wlo;
                split_pack(rh0, rh1, whi, wlo);
                pv1 = (unsigned long long)whi | ((unsigned long long)wlo << 32);
            } else {       // u-gate: local
                *reinterpret_cast<float2*>(&uS[b * 64 + (w - 8) * 8 + qa]) =
                    make_float2(sg0, sg1);
            }
        }
        {
            // ship packed value to the odd neighbor (lane+4); split rank broadcast
            unsigned long long pvu = __shfl_up_sync(0xffffffffu, pv1, 4);
            if (w < 8) {
                const int b = gp >> 1;                // invariant under pairing
                int u0 = (int)cr * 64 + w * 8 + qa;
                uint32_t off = rh_base + (uint32_t)((((u0 >> 1) * 8) + 2 * b) * 4);
                if (!(gp & 1)) {
                    dsmem_store_u64(off, 0u, pv1);
                    dsmem_store_u64(off, 1u, pv1);
                } else {
                    dsmem_store_u64(off, 2u, pvu);
                    dsmem_store_u64(off, 3u, pvu);
                }
            }
        }
        CLUSTER_SYNC();   // rh slices visible cluster-wide

        // ---- phase 2: (r*h) @ Whh strip over K-half (fused chain) ----
        float d[4] = {0.f, 0.f, 0.f, 0.f};
#pragma unroll
        for (int ch = 0; ch < 8; ch++) {
            uint32_t a[4];
            a[0] = rhAp[(kh * 64 + ch * 8 + tg) * 8 + gp];
            a[2] = rhAp[(kh * 64 + ch * 8 + tg + 4) * 8 + gp];
            a[1] = 0u; a[3] = 0u;
            MMA_BF16(d, a, b2h[ch]);
            MMA_BF16(d, a, b2l[ch]);
        }
        float y0 = d[0] + __shfl_down_sync(0xffffffffu, d[0], 4);
        float y1 = d[1] + __shfl_down_sync(0xffffffffu, d[1], 4);
        if (!(gp & 1)) {
            const int b = gp >> 1;
            *reinterpret_cast<float2*>(&red[kh * 256 + b * 64 + ns * 8 + qa]) =
                make_float2(y0, y1);
        }
        __syncthreads();

        // ---- finalize: cand + state update + output + paired h exchange ----
        if (tid < 256) {
            float v = red[r2 * 64 + c2] + red[256 + r2 * 64 + c2] + p2buf[bc][tid];
            float av = fabsf(v), e = __expf(-2.f * av);
            float cand = copysignf((1.f - e) / (1.f + e), v);
            float u = uS[r2 * 64 + c2];
            int unit = (int)cr * 64 + c2;
            float hold = h4f[unit * 4 + r2];
            float hn = u * hold + (1.f - u) * cand;
            outp[(size_t)t * UU] = hn;
            h4f[unit * 4 + r2] = hn;
            float hn1 = __shfl_down_sync(0xffffffffu, hn, 1);
            unsigned long long pv2 = 0ull;
            if (!(c2 & 1)) {
                uint32_t whi, wlo;
                split_pack(hn, hn1, whi, wlo);
                pv2 = (unsigned long long)whi | ((unsigned long long)wlo << 32);
            }
            unsigned long long pvu = __shfl_up_sync(0xffffffffu, pv2, 1);
            // (unit>>1) is invariant under the even/odd pairing
            uint32_t off = hA_base + (uint32_t)((((unit >> 1) * 8) + 2 * r2) * 4);
            if (!(c2 & 1)) {
                dsmem_store_u64(off, 0u, pv2);
                dsmem_store_u64(off, 1u, pv2);
            } else {
                dsmem_store_u64(off, 2u, pvu);
                dsmem_store_u64(off, 3u, pvu);
            }
        }
        CLUSTER_SYNC();   // h_new visible cluster-wide
    }
}

// ---------------------------------------------------------------------------
// Launch
// ---------------------------------------------------------------------------
extern "C" void kernel_launch(void* const* d_in, const int* in_sizes, int n_in,
                              void* d_out, int out_size) {
    const float* x    = (const float*)d_in[0];
    const float* iw   = (const float*)d_in[1];
    const float* hw   = (const float*)d_in[2];
    const float* bias = (const float*)d_in[3];
    float* out = (float*)d_out;

    static int attr_set = 0;
    if (!attr_set) {
        cudaFuncSetAttribute(mma_pre_kernel, cudaFuncAttributeMaxDynamicSharedMemorySize,
                             MP_SMEM_BYTES);
        attr_set = 1;
    }

    split_w_kernel<<<(GG * KK3 + 255) / 256, 256>>>(iw);
    split_x_kernel<<<(MTOT * DD / 4) / 256, 256>>>(x);

    dim3 pgrid(MTOT / 128, GG / 128);   // 1024 x 6
    mma_pre_kernel<<<pgrid, 256, MP_SMEM_BYTES>>>(bias);

    // 128 CTAs = 32 clusters of 4 (4 batch rows per cluster)
    rnn_kernel<<<BB, 512>>>(hw, out);
}

// round 15
// speedup vs baseline: 1.0431x; 1.0431x over previous
#include <cuda_runtime.h>
#include <cuda_bf16.h>
#include <math.h>
#include <stdint.h>

// Problem constants
#define BB   128     // batch
#define TT   1024    // seq
#define DD   128     // in_dim
#define UU   256     // units
#define GG   768     // 3*units (r|u|c)
#define KK3  384     // 3*in_dim (x_t | x_{t-1} | x_{t-2})
#define MTOT (BB * TT)

// ---------------------------------------------------------------------------
// PTX helpers (baseline PTX only — no sm_103a-only features)
// ---------------------------------------------------------------------------
#define CLUSTER_SYNC() do { \
    asm volatile("barrier.cluster.arrive.aligned;" ::: "memory"); \
    asm volatile("barrier.cluster.wait.aligned;" ::: "memory"); \
} while (0)

// remote SMEM stores with inline mapa (no live remote-address registers)
__device__ __forceinline__ void dsmem_store_u64(uint32_t saddr, uint32_t rank,
                                                unsigned long long v) {
    uint32_t remote;
    asm("mapa.shared::cluster.u32 %0, %1, %2;" : "=r"(remote) : "r"(saddr), "r"(rank));
    asm volatile("st.shared::cluster.b64 [%0], %1;" :: "r"(remote), "l"(v) : "memory");
}

// cp.async (sm_80+ baseline)
__device__ __forceinline__ void cp_async16(uint32_t smem, const void* g) {
    asm volatile("cp.async.cg.shared.global [%0], [%1], 16;" :: "r"(smem), "l"(g) : "memory");
}
__device__ __forceinline__ void cp_async8(uint32_t smem, const void* g) {
    asm volatile("cp.async.ca.shared.global [%0], [%1], 8;" :: "r"(smem), "l"(g) : "memory");
}
__device__ __forceinline__ void cp_async4(uint32_t smem, const void* g) {
    asm volatile("cp.async.ca.shared.global [%0], [%1], 4;" :: "r"(smem), "l"(g) : "memory");
}
#define CP_COMMIT() asm volatile("cp.async.commit_group;" ::: "memory")
#define CP_WAIT1()  asm volatile("cp.async.wait_group 1;" ::: "memory")

// bf16 m16n8k16 MMA (fragment layouts verified in rounds 5-13)
#define MMA_BF16(d, a, b) \
    asm volatile("mma.sync.aligned.m16n8k16.row.col.f32.bf16.bf16.f32 " \
        "{%0,%1,%2,%3}, {%4,%5,%6,%7}, {%8,%9}, {%0,%1,%2,%3};" \
        : "+f"((d)[0]), "+f"((d)[1]), "+f"((d)[2]), "+f"((d)[3]) \
        : "r"((a)[0]), "r"((a)[1]), "r"((a)[2]), "r"((a)[3]), "r"((b)[0]), "r"((b)[1]))

// split (a,b) fp32 pair into packed bf16x2 hi and lo words (low half = a)
__device__ __forceinline__ void split_pack(float a, float b, uint32_t& hi, uint32_t& lo) {
    __nv_bfloat16 ah = __float2bfloat16_rn(a), bh = __float2bfloat16_rn(b);
    __nv_bfloat16 al = __float2bfloat16_rn(a - __bfloat162float(ah));
    __nv_bfloat16 bl = __float2bfloat16_rn(b - __bfloat162float(bh));
    __nv_bfloat162 h2; h2.x = ah; h2.y = bh;
    __nv_bfloat162 l2; l2.x = al; l2.y = bl;
    hi = *reinterpret_cast<uint32_t*>(&h2);
    lo = *reinterpret_cast<uint32_t*>(&l2);
}

// ---------------------------------------------------------------------------
// Scratch (device globals: no allocations allowed)
// ---------------------------------------------------------------------------
__device__ __nv_bfloat16 g_xhi[(size_t)MTOT * DD];     // 32 MB
__device__ __nv_bfloat16 g_xlo[(size_t)MTOT * DD];     // 32 MB
__device__ __nv_bfloat16 g_WThi[GG * KK3];             // combined weights, [col][k3] K-major
__device__ __nv_bfloat16 g_WTlo[GG * KK3];
__device__ float g_Pre[(size_t)BB * TT * GG];          // pre-activations (402 MB)

// ---------------------------------------------------------------------------
// Kernel 1: build combined input weights, K-major, bf16 hi/lo split.
// ---------------------------------------------------------------------------
__global__ void split_w_kernel(const float* __restrict__ iw) {
    int idx = blockIdx.x * blockDim.x + threadIdx.x;
    if (idx >= GG * KK3) return;
    int j  = idx / KK3;
    int k3 = idx - j * KK3;
    int gate = j >> 8;
    int ju   = j & 255;
    int s    = k3 >> 7;
    int k    = k3 & 127;
    const float* row = iw + (size_t)k * (7 * UU);
    float v = 0.f;
    if (gate == 0) {
        float W = row[0 * UU + ju], dW = row[3 * UU + ju], ddW = row[5 * UU + ju];
        v = (s == 0) ? (W + dW + ddW) : (s == 1) ? -(dW + 2.f * ddW) : ddW;
    } else if (gate == 1) {
        float W = row[1 * UU + ju], dW = row[4 * UU + ju], ddW = row[6 * UU + ju];
        v = (s == 0) ? (W + dW + ddW) : (s == 1) ? -(dW + 2.f * ddW) : ddW;
    } else {
        v = (s == 0) ? row[2 * UU + ju] : 0.f;
    }
    __nv_bfloat16 hi = __float2bfloat16_rn(v);
    __nv_bfloat16 lo = __float2bfloat16_rn(v - __bfloat162float(hi));
    g_WThi[idx] = hi;
    g_WTlo[idx] = lo;
}

// ---------------------------------------------------------------------------
// Kernel 2: split x into bf16 hi/lo (4 elems per thread).
// ---------------------------------------------------------------------------
__global__ void split_x_kernel(const float* __restrict__ x) {
    size_t i4 = (size_t)blockIdx.x * blockDim.x + threadIdx.x;
    float4 v = reinterpret_cast<const float4*>(x)[i4];
    __nv_bfloat16 h0 = __float2bfloat16_rn(v.x), h1 = __float2bfloat16_rn(v.y);
    __nv_bfloat16 h2 = __float2bfloat16_rn(v.z), h3 = __float2bfloat16_rn(v.w);
    __nv_bfloat16 l0 = __float2bfloat16_rn(v.x - __bfloat162float(h0));
    __nv_bfloat16 l1 = __float2bfloat16_rn(v.y - __bfloat162float(h1));
    __nv_bfloat16 l2 = __float2bfloat16_rn(v.z - __bfloat162float(h2));
    __nv_bfloat16 l3 = __float2bfloat16_rn(v.w - __bfloat162float(h3));
    __nv_bfloat16 hv[4] = {h0, h1, h2, h3};
    __nv_bfloat16 lv[4] = {l0, l1, l2, l3};
    reinterpret_cast<uint2*>(g_xhi)[i4] = *reinterpret_cast<uint2*>(hv);
    reinterpret_cast<uint2*>(g_xlo)[i4] = *reinterpret_cast<uint2*>(lv);
}

// ---------------------------------------------------------------------------
// Kernel 3: tensor precompute — K=64 sub-chunks, cp.async double buffering
// (round-12 version, proven; at its HMMA-pipe compute ceiling).
// ---------------------------------------------------------------------------
#define TS2       72
#define SUB_FL    (128 * TS2)
#define SUB_BYTES (SUB_FL * 2)
#define BUF_BYTES (4 * SUB_BYTES)
#define MP_SMEM_BYTES (2 * BUF_BYTES)

__device__ __forceinline__ void ld_sub_A(char* smem_gen, uint32_t sbase,
                                         const __nv_bfloat16* __restrict__ src,
                                         int m0, int s, int half, int tid) {
#pragma unroll
    for (int i = 0; i < 4; i++) {
        int idx = tid + i * 256;
        int r   = idx >> 3;
        int c8  = (idx & 7) << 3;
        int m   = m0 + r;
        uint32_t off = (uint32_t)((r * TS2 + c8) * 2);
        if ((m & (TT - 1)) >= s)
            cp_async16(sbase + off, src + (size_t)(m - s) * DD + half * 64 + c8);
        else
            *reinterpret_cast<uint4*>(smem_gen + off) = make_uint4(0u, 0u, 0u, 0u);
    }
}

__device__ __forceinline__ void ld_sub_B(uint32_t sbase,
                                         const __nv_bfloat16* __restrict__ src,
                                         int n0, int s, int half, int tid) {
#pragma unroll
    for (int i = 0; i < 4; i++) {
        int idx = tid + i * 256;
        int r   = idx >> 3;
        int c8  = (idx & 7) << 3;
        uint32_t off = (uint32_t)((r * TS2 + c8) * 2);
        cp_async16(sbase + off, src + (size_t)(n0 + r) * KK3 + s * 128 + half * 64 + c8);
    }
}

__global__ void __launch_bounds__(256, 1) mma_pre_kernel(const float* __restrict__ bias) {
    extern __shared__ char smc[];
    const uint32_t sb = (uint32_t)__cvta_generic_to_shared(smc);

    const int tid  = threadIdx.x;
    const int wid  = tid >> 5;
    const int lane = tid & 31;
    const int wm   = wid & 3;
    const int wn   = wid >> 2;
    const int m0 = blockIdx.x * 128;
    const int n0 = blockIdx.y * 128;
    const int Q  = (n0 < 512) ? 6 : 2;

    const int qa = (lane & 3) * 2;
    const int gp = lane >> 2;

    float acc[2][8][4];
#pragma unroll
    for (int mf = 0; mf < 2; mf++)
#pragma unroll
        for (int nf = 0; nf < 8; nf++)
#pragma unroll
            for (int q = 0; q < 4; q++) acc[mf][nf][q] = 0.f;

    ld_sub_A(smc, sb + 0 * SUB_BYTES, g_xhi, m0, 0, 0, tid);
    ld_sub_A(smc + SUB_BYTES, sb + 1 * SUB_BYTES, g_xlo, m0, 0, 0, tid);
    ld_sub_B(sb + 2 * SUB_BYTES, g_WThi, n0, 0, 0, tid);
    ld_sub_B(sb + 3 * SUB_BYTES, g_WTlo, n0, 0, 0, tid);
    CP_COMMIT();

    for (int q = 0; q < Q; q++) {
        const int bc = q & 1, bn = bc ^ 1;
        if (q + 1 < Q) {
            int s2 = (q + 1) >> 1, h2 = (q + 1) & 1;
            char*    gb = smc + bn * BUF_BYTES;
            uint32_t ab = sb + (uint32_t)bn * BUF_BYTES;
            ld_sub_A(gb, ab + 0 * SUB_BYTES, g_xhi, m0, s2, h2, tid);
            ld_sub_A(gb + SUB_BYTES, ab + 1 * SUB_BYTES, g_xlo, m0, s2, h2, tid);
            ld_sub_B(ab + 2 * SUB_BYTES, g_WThi, n0, s2, h2, tid);
            ld_sub_B(ab + 3 * SUB_BYTES, g_WTlo, n0, s2, h2, tid);
        }
        CP_COMMIT();
        CP_WAIT1();
        __syncthreads();

        const __nv_bfloat16* Ahi = reinterpret_cast<__nv_bfloat16*>(smc + bc * BUF_BYTES);
        const __nv_bfloat16* Alo = Ahi + SUB_FL;
        const __nv_bfloat16* Bhi = Alo + SUB_FL;
        const __nv_bfloat16* Blo = Bhi + SUB_FL;

#pragma unroll
        for (int ks = 0; ks < 4; ks++) {
            const int k0 = ks * 16;
            uint32_t ah[2][4], al[2][4];
#pragma unroll
            for (int mf = 0; mf < 2; mf++) {
                int r = wm * 32 + mf * 16 + gp;
                ah[mf][0] = *reinterpret_cast<const uint32_t*>(&Ahi[r * TS2 + k0 + qa]);
                ah[mf][1] = *reinterpret_cast<const uint32_t*>(&Ahi[(r + 8) * TS2 + k0 + qa]);
                ah[mf][2] = *reinterpret_cast<const uint32_t*>(&Ahi[r * TS2 + k0 + 8 + qa]);
                ah[mf][3] = *reinterpret_cast<const uint32_t*>(&Ahi[(r + 8) * TS2 + k0 + 8 + qa]);
                al[mf][0] = *reinterpret_cast<const uint32_t*>(&Alo[r * TS2 + k0 + qa]);
                al[mf][1] = *reinterpret_cast<const uint32_t*>(&Alo[(r + 8) * TS2 + k0 + qa]);
                al[mf][2] = *reinterpret_cast<const uint32_t*>(&Alo[r * TS2 + k0 + 8 + qa]);
                al[mf][3] = *reinterpret_cast<const uint32_t*>(&Alo[(r + 8) * TS2 + k0 + 8 + qa]);
            }
            uint32_t bh[8][2], bl[8][2];
#pragma unroll
            for (int nf = 0; nf < 8; nf++) {
                int n = wn * 64 + nf * 8 + gp;
                bh[nf][0] = *reinterpret_cast<const uint32_t*>(&Bhi[n * TS2 + k0 + qa]);
                bh[nf][1] = *reinterpret_cast<const uint32_t*>(&Bhi[n * TS2 + k0 + 8 + qa]);
                bl[nf][0] = *reinterpret_cast<const uint32_t*>(&Blo[n * TS2 + k0 + qa]);
                bl[nf][1] = *reinterpret_cast<const uint32_t*>(&Blo[n * TS2 + k0 + 8 + qa]);
            }
#pragma unroll
            for (int mf = 0; mf < 2; mf++)
#pragma unroll
                for (int nf = 0; nf < 8; nf++) {
                    MMA_BF16(acc[mf][nf], ah[mf], bh[nf]);
                    MMA_BF16(acc[mf][nf], ah[mf], bl[nf]);
                    MMA_BF16(acc[mf][nf], al[mf], bh[nf]);
                }
        }
        __syncthreads();
    }

#pragma unroll
    for (int nf = 0; nf < 8; nf++) {
        int col = n0 + wn * 64 + nf * 8 + qa;
        float2 bz = *reinterpret_cast<const float2*>(bias + col);
#pragma unroll
        for (int mf = 0; mf < 2; mf++) {
            int row = m0 + wm * 32 + mf * 16 + gp;
            float2 v0, v1;
            v0.x = acc[mf][nf][0] + bz.x;
            v0.y = acc[mf][nf][1] + bz.y;
            v1.x = acc[mf][nf][2] + bz.x;
            v1.y = acc[mf][nf][3] + bz.y;
            *reinterpret_cast<float2*>(&g_Pre[(size_t)row * GG + col]) = v0;
            *reinterpret_cast<float2*>(&g_Pre[(size_t)(row + 8) * GG + col]) = v1;
        }
    }
}

// ---------------------------------------------------------------------------
// Kernel 4: HMMA recurrence — R13 structure, byte-equivalent math, with ONE
// change: phase-2 weight fragments live in dynamic SMEM (uint4 per warp/chunk/
// lane, conflict-free LDS.128), freeing 32 registers vs the 128-reg cap.
// ---------------------------------------------------------------------------
__global__ void __launch_bounds__(512, 1) __cluster_dims__(4, 1, 1)
rnn_kernel(const float* __restrict__ Wh, float* __restrict__ out) {
    extern __shared__ uint4 w2s[];    // [16 warps][8 chunks][32 lanes] = 64 KB
    __shared__ uint32_t hAp[1024];    // [128 unit-pairs][8 rows] interleaved hi/lo
    __shared__ uint32_t rhAp[1024];
    __shared__ float h4f[1024];       // [unit][row] fp32 hidden state
    __shared__ float uS[256];         // [row][col] update gate slice
    __shared__ float red[512];        // [kh][row][col] phase2 reduction
    __shared__ float2 p1buf[2][256];  // prefetched phase-1 pre-activations
    __shared__ float  p2buf[2][256];  // prefetched cand pre-activations

    const int tid  = threadIdx.x;
    const int w    = tid >> 5;
    const int lane = tid & 31;
    const int gp   = lane >> 2;
    const int tg   = lane & 3;
    const int qa   = tg * 2;
    uint32_t cr;
    asm("mov.u32 %0, %%cluster_ctarank;" : "=r"(cr));
    const int b0 = (blockIdx.x >> 2) * 4;

    // ---- one-time: phase-1 weight fragments in registers (bf16 hi/lo) ----
    uint32_t b1h[16][2], b1l[16][2];
    {
        int gcol = (w < 8) ? ((int)cr * 64 + w * 8 + gp)
                           : (256 + (int)cr * 64 + (w - 8) * 8 + gp);
#pragma unroll
        for (int ch = 0; ch < 16; ch++) {
            int k0 = ch * 16;
            float v00 = Wh[(size_t)(k0 + qa) * GG + gcol];
            float v01 = Wh[(size_t)(k0 + qa + 1) * GG + gcol];
            float v10 = Wh[(size_t)(k0 + 8 + qa) * GG + gcol];
            float v11 = Wh[(size_t)(k0 + 8 + qa + 1) * GG + gcol];
            split_pack(v00, v01, b1h[ch][0], b1l[ch][0]);
            split_pack(v10, v11, b1h[ch][1], b1l[ch][1]);
        }
    }
    // ---- one-time: phase-2 weight fragments into SMEM (frees 32 regs) ----
    const int ns = w & 7, kh = w >> 3;
    {
        int gcol = 512 + (int)cr * 64 + ns * 8 + gp;
#pragma unroll
        for (int ch = 0; ch < 8; ch++) {
            int k0 = kh * 128 + ch * 16;
            float v00 = Wh[(size_t)(k0 + qa) * GG + gcol];
            float v01 = Wh[(size_t)(k0 + qa + 1) * GG + gcol];
            float v10 = Wh[(size_t)(k0 + 8 + qa) * GG + gcol];
            float v11 = Wh[(size_t)(k0 + 8 + qa + 1) * GG + gcol];
            uint32_t h0, l0, h1, l1;
            split_pack(v00, v01, h0, l0);
            split_pack(v10, v11, h1, l1);
            w2s[(w * 8 + ch) * 32 + lane] = make_uint4(h0, h1, l0, l1);
        }
    }

    // ---- init state ----
    for (int i = tid; i < 1024; i += 512) { hAp[i] = 0u; h4f[i] = 0.f; }
    const uint32_t rh_base = (uint32_t)__cvta_generic_to_shared(rhAp);
    const uint32_t hA_base = (uint32_t)__cvta_generic_to_shared(hAp);
    __syncthreads();
    CLUSTER_SYNC();

    // finalize-2 identities
    const int r2 = (tid >> 6) & 3;
    const int c2 = tid & 63;
    const float* p2ptr = g_Pre + (size_t)(b0 + r2) * TT * GG + 512 + cr * 64 + c2;
    float* outp = out + ((size_t)(b0 + r2) * TT) * UU + cr * 64 + c2;

    // phase-1 p1 prefetch pointer (prefetching lanes 0-15: batch = gp, col qa)
    const int colbase1 = (w < 8) ? ((int)cr * 64 + w * 8 + qa)
                                 : (256 + (int)cr * 64 + (w - 8) * 8 + qa);
    const float* p1ptr = g_Pre + (size_t)(b0 + (gp & 3)) * TT * GG + colbase1;

    const uint32_t p1slot = (uint32_t)__cvta_generic_to_shared(&p1buf[0][w * 16 + lane]);
    const uint32_t p2slot = (uint32_t)__cvta_generic_to_shared(&p2buf[0][tid]);

    // prologue: prefetch step 0
    if (lane < 16) cp_async8(p1slot, p1ptr);
    if (tid < 256) cp_async4(p2slot, p2ptr);
    CP_COMMIT();

    for (int t = 0; t < TT; t++) {
        const int tn = (t + 1) & (TT - 1);
        const int bc = t & 1, bn = bc ^ 1;

        if (lane < 16) cp_async8(p1slot + (uint32_t)bn * 2048u, p1ptr + (size_t)tn * GG);
        if (tid < 256) cp_async4(p2slot + (uint32_t)bn * 1024u, p2ptr + (size_t)tn * GG);
        CP_COMMIT();

        // ---- phase 1: h @ [Whr|Whu] strip, split hi/lo chains ----
        float chA[4] = {0.f, 0.f, 0.f, 0.f};
        float clA[4] = {0.f, 0.f, 0.f, 0.f};
#pragma unroll
        for (int ch = 0; ch < 16; ch++) {
            uint32_t a[4];
            a[0] = hAp[(ch * 8 + tg) * 8 + gp];
            a[2] = hAp[(ch * 8 + tg + 4) * 8 + gp];
            a[1] = 0u; a[3] = 0u;
            MMA_BF16(chA, a, b1h[ch]);
            MMA_BF16(clA, a, b1l[ch]);
        }
        CP_WAIT1();
        float v0 = chA[0] + clA[0];
        float v1 = chA[1] + clA[1];
        v0 += __shfl_down_sync(0xffffffffu, v0, 4);   // row 2b + row 2b+1 (hi+lo)
        v1 += __shfl_down_sync(0xffffffffu, v1, 4);
        if (!(gp & 1)) {
            const int b = gp >> 1;                    // batch row 0..3
            float2 p1 = p1buf[bc][w * 16 + b * 4 + tg];
            v0 += p1.x; v1 += p1.y;
            float sg0 = 1.f / (1.f + __expf(-v0));
            float sg1 = 1.f / (1.f + __expf(-v1));
            if (w < 8) {   // r-gate: produce rh, fused u64 broadcast
                int u0 = (int)cr * 64 + w * 8 + qa;
                float rh0 = sg0 * h4f[u0 * 4 + b];
                float rh1 = sg1 * h4f[(u0 + 1) * 4 + b];
                uint32_t whi, wlo;
                split_pack(rh0, rh1, whi, wlo);
                unsigned long long pv = (unsigned long long)whi |
                                        ((unsigned long long)wlo << 32);
                uint32_t off = rh_base + (uint32_t)((((u0 >> 1) * 8) + 2 * b) * 4);
#pragma unroll
                for (int rr = 0; rr < 4; rr++)
                    dsmem_store_u64(off, (uint32_t)rr, pv);
            } else {       // u-gate: local
                *reinterpret_cast<float2*>(&uS[b * 64 + (w - 8) * 8 + qa]) =
                    make_float2(sg0, sg1);
            }
        }
        CLUSTER_SYNC();   // rh slices visible cluster-wide

        // ---- phase 2: (r*h) @ Whh strip over K-half, weights from SMEM ----
        float d[4] = {0.f, 0.f, 0.f, 0.f};
#pragma unroll
        for (int ch = 0; ch < 8; ch++) {
            uint4 wv = w2s[(w * 8 + ch) * 32 + lane];
            uint32_t bhw[2] = {wv.x, wv.y};
            uint32_t blw[2] = {wv.z, wv.w};
            uint32_t a[4];
            a[0] = rhAp[(kh * 64 + ch * 8 + tg) * 8 + gp];
            a[2] = rhAp[(kh * 64 + ch * 8 + tg + 4) * 8 + gp];
            a[1] = 0u; a[3] = 0u;
            MMA_BF16(d, a, bhw);
            MMA_BF16(d, a, blw);
        }
        float y0 = d[0] + __shfl_down_sync(0xffffffffu, d[0], 4);
        float y1 = d[1] + __shfl_down_sync(0xffffffffu, d[1], 4);
        if (!(gp & 1)) {
            const int b = gp >> 1;
            *reinterpret_cast<float2*>(&red[kh * 256 + b * 64 + ns * 8 + qa]) =
                make_float2(y0, y1);
        }
        __syncthreads();

        // ---- finalize: cand + state update + output + fused h exchange ----
        if (tid < 256) {
            float v = red[r2 * 64 + c2] + red[256 + r2 * 64 + c2] + p2buf[bc][tid];
            float av = fabsf(v), e = __expf(-2.f * av);
            float cand = copysignf((1.f - e) / (1.f + e), v);
            float u = uS[r2 * 64 + c2];
            int unit = (int)cr * 64 + c2;
            float hold = h4f[unit * 4 + r2];
            float hn = u * hold + (1.f - u) * cand;
            outp[(size_t)t * UU] = hn;
            h4f[unit * 4 + r2] = hn;
            float hn1 = __shfl_down_sync(0xffffffffu, hn, 1);
            if (!(c2 & 1)) {
                uint32_t whi, wlo;
                split_pack(hn, hn1, whi, wlo);
                unsigned long long pv = (unsigned long long)whi |
                                        ((unsigned long long)wlo << 32);
                uint32_t off = hA_base + (uint32_t)((((unit >> 1) * 8) + 2 * r2) * 4);
#pragma unroll
                for (int rr = 0; rr < 4; rr++)
                    dsmem_store_u64(off, (uint32_t)rr, pv);
            }
        }
        CLUSTER_SYNC();   // h_new visible cluster-wide
    }
}

// ---------------------------------------------------------------------------
// Launch
// ---------------------------------------------------------------------------
#define RNN_DSMEM (16 * 8 * 32 * 16)   // 65536 B for w2s

extern "C" void kernel_launch(void* const* d_in, const int* in_sizes, int n_in,
                              void* d_out, int out_size) {
    const float* x    = (const float*)d_in[0];
    const float* iw   = (const float*)d_in[1];
    const float* hw   = (const float*)d_in[2];
    const float* bias = (const float*)d_in[3];
    float* out = (float*)d_out;

    static int attr_set = 0;
    if (!attr_set) {
        cudaFuncSetAttribute(mma_pre_kernel, cudaFuncAttributeMaxDynamicSharedMemorySize,
                             MP_SMEM_BYTES);
        cudaFuncSetAttribute(rnn_kernel, cudaFuncAttributeMaxDynamicSharedMemorySize,
                             RNN_DSMEM);
        attr_set = 1;
    }

    split_w_kernel<<<(GG * KK3 + 255) / 256, 256>>>(iw);
    split_x_kernel<<<(MTOT * DD / 4) / 256, 256>>>(x);

    dim3 pgrid(MTOT / 128, GG / 128);   // 1024 x 6
    mma_pre_kernel<<<pgrid, 256, MP_SMEM_BYTES>>>(bias);

    // 128 CTAs = 32 clusters of 4 (4 batch rows per cluster)
    rnn_kernel<<<BB, 512, RNN_DSMEM>>>(hw, out);
}